// round 14
// baseline (speedup 1.0000x reference)
#include <cuda_runtime.h>
#include <cuda_fp16.h>
#include <cstdint>

// ---------------- problem-size scratch (static device globals; no allocs) ---
#define NMAX 100096
#define EMAX 1600256
#define ENMAX (NMAX + EMAX)
#define POOLB 592

__device__ int    g_not64;               // 1 if edge_index is int32
__device__ int    g_deg[NMAX];
__device__ int    g_rp[NMAX + 1];        // CSR row pointers (by SRC)
__device__ int    g_cur[NMAX];
__device__ int    g_bsum[128];
__device__ int    g_sd[ENMAX];           // dst per CSR slot (src-sorted)
__device__ float  g_u1[128], g_v1[128];  // W1 @ att_src1 / att_dst1
__device__ float  g_h2[NMAX * 64];       // layer2 features, row-major
__device__ float  g_as1[NMAX], g_ad1[NMAX];
__device__ float  g_as2[NMAX], g_ad2[NMAX];
__device__ float  g_acc[NMAX * 64];      // layer1 scatter accumulator
__device__ float  g_den[NMAX];           // layer1 softmax denominators
__device__ float  g_den2[NMAX];          // layer2 softmax denominators
__device__ float  g_pool[POOLB * 64];    // pool partials

// ---------------- init ------------------------------------------------------
__global__ void k_zero(int n) {
    int i = blockIdx.x * blockDim.x + threadIdx.x;
    if (i < n) g_deg[i] = 0;
    if (i == 0) g_not64 = 0;
}

// ---------------- edge-index dtype detection --------------------------------
__global__ void k_detect(const long long* __restrict__ ei, int nq) {
    int i = blockIdx.x * blockDim.x + threadIdx.x;
    if (i < nq && ((unsigned long long)ei[i] >> 32) != 0ull) atomicOr(&g_not64, 1);
}

__device__ __forceinline__ int load_idx(const void* ei, long long pos) {
    if (g_not64) return ((const int*)ei)[pos];
    return (int)((const long long*)ei)[pos];
}

__device__ __forceinline__ int clampi(int v, int n) {
    v = v < 0 ? 0 : v;
    return v >= n ? n - 1 : v;
}

// ---------------- u1 = W1 @ att_s, v1 = W1 @ att_d (1 block, 128 thr) --------
__global__ void k_wv(const float* __restrict__ Wg, const float* __restrict__ att_s,
                     const float* __restrict__ att_d) {
    __shared__ float as_[64], ad_[64];
    int t = threadIdx.x;
    if (t < 64) { as_[t] = att_s[t]; ad_[t] = att_d[t]; }
    __syncthreads();
    float u = 0.f, v = 0.f;
    const float* wr = Wg + (size_t)t * 64;
#pragma unroll 16
    for (int c = 0; c < 64; c++) { float w = wr[c]; u += w * as_[c]; v += w * ad_[c]; }
    g_u1[t] = u;
    g_v1[t] = v;
}

// ---------------- AS1/AD1 = X . u1 / X . v1 (warp per 4 rows) ----------------
__global__ void __launch_bounds__(256)
k_mv1(const float* __restrict__ X, float* __restrict__ AS, float* __restrict__ AD,
      int n) {
    __shared__ float4 us[32], vs[32];
    int tid = threadIdx.x;
    if (tid < 32) { us[tid] = ((const float4*)g_u1)[tid]; vs[tid] = ((const float4*)g_v1)[tid]; }
    __syncthreads();
    int warp = tid >> 5, lane = tid & 31;
    int r0 = (blockIdx.x * 8 + warp) * 4;
    if (r0 >= n) return;

    float4 xv[4];
#pragma unroll
    for (int rr = 0; rr < 4; rr++) {
        int row = r0 + rr < n ? r0 + rr : n - 1;
        xv[rr] = ((const float4*)(X + (size_t)row * 128))[lane];
    }
    float4 u = us[lane], v = vs[lane];
#pragma unroll
    for (int rr = 0; rr < 4; rr++) {
        float ps = xv[rr].x * u.x + xv[rr].y * u.y + xv[rr].z * u.z + xv[rr].w * u.w;
        float pd = xv[rr].x * v.x + xv[rr].y * v.y + xv[rr].z * v.z + xv[rr].w * v.w;
#pragma unroll
        for (int o = 16; o; o >>= 1) {
            ps += __shfl_xor_sync(0xffffffffu, ps, o);
            pd += __shfl_xor_sync(0xffffffffu, pd, o);
        }
        if (lane == 0 && r0 + rr < n) { AS[r0 + rr] = ps; AD[r0 + rr] = pd; }
    }
}

// ---------------- out-degree histogram (by SRC, incl. self loops) ------------
__global__ void k_hist(const void* __restrict__ ei, int E, int EN, int n) {
    int i = blockIdx.x * blockDim.x + threadIdx.x;
    if (i >= EN) return;
    int s = (i < E) ? clampi(load_idx(ei, i), n) : (i - E);
    atomicAdd(&g_deg[s], 1);
}

// ---------------- prefix scan -------------------------------------------------
__global__ void k_scan_block(int n) {
    __shared__ int s[1024];
    int i = blockIdx.x * 1024 + threadIdx.x;
    int v = (i < n) ? g_deg[i] : 0;
    s[threadIdx.x] = v;
    __syncthreads();
#pragma unroll
    for (int o = 1; o < 1024; o <<= 1) {
        int t = (threadIdx.x >= (unsigned)o) ? s[threadIdx.x - o] : 0;
        __syncthreads();
        s[threadIdx.x] += t;
        __syncthreads();
    }
    if (i < n) g_rp[i] = s[threadIdx.x] - v;
    if (threadIdx.x == 1023) g_bsum[blockIdx.x] = s[1023];
}

__global__ void k_scan_top(int nb) {
    __shared__ int s[128];
    int t = threadIdx.x;
    int v = (t < nb) ? g_bsum[t] : 0;
    s[t] = v;
    __syncthreads();
#pragma unroll
    for (int o = 1; o < 128; o <<= 1) {
        int tv = (t >= (unsigned)o) ? s[t - o] : 0;
        __syncthreads();
        s[t] += tv;
        __syncthreads();
    }
    if (t < nb) g_bsum[t] = s[t] - v;
}

__global__ void k_scan_add(int n, int total) {
    int i = blockIdx.x * blockDim.x + threadIdx.x;
    if (i < n) {
        int v = g_rp[i] + g_bsum[i >> 10];
        g_rp[i] = v;
        g_cur[i] = v;
    }
    if (i == 0) g_rp[n] = total;
}

// ---------------- scatter edges into src-CSR order (store dst) --------------
__global__ void k_scatter(const void* __restrict__ ei, int E, int EN, int n) {
    int i = blockIdx.x * blockDim.x + threadIdx.x;
    if (i >= EN) return;
    int s, d;
    if (i < E) {
        s = clampi(load_idx(ei, i), n);
        d = clampi(load_idx(ei, (long long)E + i), n);
    } else { s = i - E; d = s; }
    int pos = atomicAdd(&g_cur[s], 1);
    if (pos >= 0 && pos < ENMAX) g_sd[pos] = d;
}

// ---------------- zero accumulators ------------------------------------------
__global__ void k_zeroacc(int n) {
    int total = n * 16;   // float4 count
    float4 z = make_float4(0.f, 0.f, 0.f, 0.f);
    for (int i = blockIdx.x * blockDim.x + threadIdx.x; i < total;
         i += gridDim.x * blockDim.x) {
        ((float4*)g_acc)[i] = z;
        if (i < n) { g_den[i] = 0.f; g_den2[i] = 0.f; }
    }
}

// ---------------- red helper --------------------------------------------------
__device__ __forceinline__ void red_v4(float* p, float a, float b, float c, float d) {
    asm volatile("red.global.add.v4.f32 [%0], {%1, %2, %3, %4};"
                 :: "l"(p), "f"(a), "f"(b), "f"(c), "f"(d) : "memory");
}

// ---------------- SGEMM1 (128->64) with FUSED softmax scatter ----------------
__global__ void __launch_bounds__(256)
k_sgemm128s(const float* __restrict__ X, const float* __restrict__ Wg,
            const float* __restrict__ AS, const float* __restrict__ AD, int n) {
    __shared__ float xs[64 * 68];   // staging (stride 64 + XOR) then out tile (stride 68)
    __shared__ float ws[64 * 64];
    __shared__ float sAS[64];
    __shared__ int   srp[65];

    int tid = threadIdx.x;
    int i = tid >> 4, j = tid & 15;
    int base = blockIdx.x * 64;

    if (tid < 64) sAS[tid] = AS[base + tid < n ? base + tid : n - 1];
    if (tid < 65) srp[tid] = g_rp[base + tid < n ? base + tid : n];

    float acc[4][4];
#pragma unroll
    for (int r = 0; r < 4; r++)
#pragma unroll
        for (int c = 0; c < 4; c++) acc[r][c] = 0.f;

#pragma unroll
    for (int ph = 0; ph < 2; ph++) {
        __syncthreads();
#pragma unroll
        for (int t = tid; t < 1024; t += 256) {
            int row = t >> 4, c4 = t & 15;
            int rc = base + row < n ? base + row : n - 1;
            float4 v = *(const float4*)(X + (size_t)rc * 128 + ph * 64 + c4 * 4);
            int g0 = row >> 2, r3 = row & 3;
#pragma unroll
            for (int s = 0; s < 4; s++) {
                int k = c4 * 4 + s;
                float val = (s == 0) ? v.x : (s == 1) ? v.y : (s == 2) ? v.z : v.w;
                xs[k * 64 + ((g0 ^ (k & 15)) << 2) + r3] = val;
            }
        }
#pragma unroll
        for (int t = tid; t < 1024; t += 256) {
            int k = t >> 4, c4 = t & 15;
            *(float4*)(ws + k * 64 + c4 * 4) =
                *(const float4*)(Wg + (size_t)(ph * 64 + k) * 64 + c4 * 4);
        }
        __syncthreads();

#pragma unroll 4
        for (int k = 0; k < 64; k++) {
            float4 a = *(const float4*)(xs + k * 64 + ((i ^ (k & 15)) << 2));
            float4 b = *(const float4*)(ws + k * 64 + j * 4);
            acc[0][0] += a.x * b.x; acc[0][1] += a.x * b.y;
            acc[0][2] += a.x * b.z; acc[0][3] += a.x * b.w;
            acc[1][0] += a.y * b.x; acc[1][1] += a.y * b.y;
            acc[1][2] += a.y * b.z; acc[1][3] += a.y * b.w;
            acc[2][0] += a.z * b.x; acc[2][1] += a.z * b.y;
            acc[2][2] += a.z * b.z; acc[2][3] += a.z * b.w;
            acc[3][0] += a.w * b.x; acc[3][1] += a.w * b.y;
            acc[3][2] += a.w * b.z; acc[3][3] += a.w * b.w;
        }
    }

    // ---- epilogue: stage out tile row-major (stride 68), then scatter ----
    __syncthreads();
#pragma unroll
    for (int rr = 0; rr < 4; rr++)
        *(float4*)(xs + (i * 4 + rr) * 68 + j * 4) =
            make_float4(acc[rr][0], acc[rr][1], acc[rr][2], acc[rr][3]);
    __syncthreads();

    int warp = tid >> 5, lane = tid & 31;
    int q = lane & 15, half = lane >> 4;
    for (int lr = warp * 8; lr < warp * 8 + 8; lr++) {
        int beg = srp[lr], end = srp[lr + 1];
        if (beg >= end) continue;
        float4 hv = *(const float4*)(xs + lr * 68 + q * 4);
        float as_v = sAS[lr];
        int jj = beg;
        for (; jj + 1 < end; jj += 2) {
            int d = g_sd[jj + half];
            float e = as_v + AD[d];
            e = (e > 0.f) ? e : 0.2f * e;
            float w = __expf(e);
            float* ap = g_acc + (size_t)d * 64 + q * 4;
            red_v4(ap, w * hv.x, w * hv.y, w * hv.z, w * hv.w);
            if (q == 0) atomicAdd(&g_den[d], w);
        }
        if (jj < end && half == 0) {
            int d = g_sd[jj];
            float e = as_v + AD[d];
            e = (e > 0.f) ? e : 0.2f * e;
            float w = __expf(e);
            float* ap = g_acc + (size_t)d * 64 + q * 4;
            red_v4(ap, w * hv.x, w * hv.y, w * hv.z, w * hv.w);
            if (q == 0) atomicAdd(&g_den[d], w);
        }
    }
}

// ---------------- SGEMM2 (64->64) with fused normalize+bias+relu on input ----
__global__ void __launch_bounds__(256)
k_sgemm64f(const float* __restrict__ Wg, const float* __restrict__ b1,
           const float* __restrict__ att_s, const float* __restrict__ att_d,
           float* __restrict__ H, float* __restrict__ AS, float* __restrict__ AD,
           int n) {
    __shared__ float xs[64 * 64];
    __shared__ float ws[64 * 64];
    __shared__ float atts[64], attd[64], bs[64];
    __shared__ float asd[128];

    int tid = threadIdx.x;
    int i = tid >> 4, j = tid & 15;
    int base = blockIdx.x * 64;

    if (tid < 64) { atts[tid] = att_s[tid]; attd[tid] = att_d[tid]; bs[tid] = b1[tid]; }
    if (tid < 128) asd[tid] = 0.f;
    __syncthreads();

#pragma unroll
    for (int t = tid; t < 1024; t += 256) {
        int row = t >> 4, c4 = t & 15;
        int rc = base + row < n ? base + row : n - 1;
        float inv = 1.f / (g_den[rc] + 1e-16f);
        float4 v = *(const float4*)(g_acc + (size_t)rc * 64 + c4 * 4);
        int g0 = row >> 2, r3 = row & 3;
#pragma unroll
        for (int s = 0; s < 4; s++) {
            int k = c4 * 4 + s;
            float val = (s == 0) ? v.x : (s == 1) ? v.y : (s == 2) ? v.z : v.w;
            val = fmaxf(val * inv + bs[k], 0.f);
            xs[k * 64 + ((g0 ^ (k & 15)) << 2) + r3] = val;
        }
    }
#pragma unroll
    for (int t = tid; t < 1024; t += 256) {
        int k = t >> 4, c4 = t & 15;
        *(float4*)(ws + k * 64 + c4 * 4) =
            *(const float4*)(Wg + (size_t)k * 64 + c4 * 4);
    }
    __syncthreads();

    float acc[4][4];
#pragma unroll
    for (int r = 0; r < 4; r++)
#pragma unroll
        for (int c = 0; c < 4; c++) acc[r][c] = 0.f;

#pragma unroll 4
    for (int k = 0; k < 64; k++) {
        float4 a = *(const float4*)(xs + k * 64 + ((i ^ (k & 15)) << 2));
        float4 b = *(const float4*)(ws + k * 64 + j * 4);
        acc[0][0] += a.x * b.x; acc[0][1] += a.x * b.y;
        acc[0][2] += a.x * b.z; acc[0][3] += a.x * b.w;
        acc[1][0] += a.y * b.x; acc[1][1] += a.y * b.y;
        acc[1][2] += a.y * b.z; acc[1][3] += a.y * b.w;
        acc[2][0] += a.z * b.x; acc[2][1] += a.z * b.y;
        acc[2][2] += a.z * b.z; acc[2][3] += a.z * b.w;
        acc[3][0] += a.w * b.x; acc[3][1] += a.w * b.y;
        acc[3][2] += a.w * b.z; acc[3][3] += a.w * b.w;
    }

#pragma unroll
    for (int rr = 0; rr < 4; rr++) {
        int row = base + i * 4 + rr;
        if (row < n) {
            float4 o = make_float4(acc[rr][0], acc[rr][1], acc[rr][2], acc[rr][3]);
            *(float4*)(H + (size_t)row * 64 + j * 4) = o;
            float ps = acc[rr][0] * atts[j * 4] + acc[rr][1] * atts[j * 4 + 1]
                     + acc[rr][2] * atts[j * 4 + 2] + acc[rr][3] * atts[j * 4 + 3];
            float pd = acc[rr][0] * attd[j * 4] + acc[rr][1] * attd[j * 4 + 1]
                     + acc[rr][2] * attd[j * 4 + 2] + acc[rr][3] * attd[j * 4 + 3];
            atomicAdd(&asd[i * 4 + rr], ps);
            atomicAdd(&asd[64 + i * 4 + rr], pd);
        }
    }
    __syncthreads();
    if (tid < 64 && base + tid < n) {
        AS[base + tid] = asd[tid];
        AD[base + tid] = asd[64 + tid];
    }
}

// ---------------- layer-2 denominators (warp per SRC) ------------------------
__global__ void __launch_bounds__(256)
k_den2(const float* __restrict__ AS, const float* __restrict__ AD, int n) {
    int src = (blockIdx.x * blockDim.x + threadIdx.x) >> 5;
    int lane = threadIdx.x & 31;
    if (src >= n) return;
    float as_v = AS[src];
    int beg = g_rp[src], end = g_rp[src + 1];
    for (int j = beg + lane; j < end; j += 32) {
        int d = g_sd[j];
        float e = as_v + AD[d];
        e = (e > 0.f) ? e : 0.2f * e;
        atomicAdd(&g_den2[d], __expf(e));
    }
}

// ---------------- layer-2 collapsed aggregation+pool (recompute w) -----------
__global__ void __launch_bounds__(256)
k_coefpool(const float* __restrict__ H2, const float* __restrict__ AS,
           const float* __restrict__ AD, int n) {
    __shared__ float sm[8][64];
    int warp = threadIdx.x >> 5, lane = threadIdx.x & 31;
    int gw = blockIdx.x * 8 + warp;
    int stride = gridDim.x * 8;

    float acc0 = 0.f, acc1 = 0.f;
    for (int src = gw; src < n; src += stride) {
        int beg = g_rp[src], end = g_rp[src + 1];
        float as_v = AS[src];
        float a = 0.f;
        for (int j = beg + lane; j < end; j += 32) {
            int d = g_sd[j];
            float e = as_v + AD[d];
            e = (e > 0.f) ? e : 0.2f * e;
            a += __expf(e) / (g_den2[d] + 1e-16f);
        }
#pragma unroll
        for (int o = 16; o; o >>= 1) a += __shfl_xor_sync(0xffffffffu, a, o);
        const float* hp = H2 + (size_t)src * 64;
        acc0 += a * hp[lane];
        acc1 += a * hp[lane + 32];
    }
    sm[warp][lane] = acc0;
    sm[warp][lane + 32] = acc1;
    __syncthreads();
    if (threadIdx.x < 64) {
        float v = 0.f;
#pragma unroll
        for (int w = 0; w < 8; w++) v += sm[w][threadIdx.x];
        g_pool[blockIdx.x * 64 + threadIdx.x] = v;
    }
}

// ---------------- final reduce + bias ----------------------------------------
__global__ void k_pool_b(const float* __restrict__ b2, float* __restrict__ out,
                         int n) {
    int col = threadIdx.x;   // 64 threads
    float acc = 0.f;
    for (int b = 0; b < POOLB; b++) acc += g_pool[b * 64 + col];
    out[col] = acc * (1.0f / (float)n) + b2[col];
}

// ---------------- launch ----------------------------------------------------
extern "C" void kernel_launch(void* const* d_in, const int* in_sizes, int n_in,
                              void* d_out, int out_size) {
    const float* x   = (const float*)d_in[0];
    const void*  ei  = d_in[1];
    const float* W1  = (const float*)d_in[3];
    const float* as1 = (const float*)d_in[4];
    const float* ad1 = (const float*)d_in[5];
    const float* b1  = (const float*)d_in[6];
    const float* W2  = (const float*)d_in[7];
    const float* as2 = (const float*)d_in[8];
    const float* ad2 = (const float*)d_in[9];
    const float* b2  = (const float*)d_in[10];
    float* out = (float*)d_out;

    int n  = in_sizes[0] / 128;   // N nodes
    int E  = in_sizes[1] / 2;     // edges
    int EN = E + n;               // edges + self loops

    int sgemmBlocks = (n + 63) / 64;
    int aggBlocks   = (n + 7) / 8;
    int nb          = (n + 1023) / 1024;

    // side stream + events, created once (host objects only; no device memory)
    static cudaStream_t s2 = [] {
        cudaStream_t s; cudaStreamCreateWithFlags(&s, cudaStreamNonBlocking); return s;
    }();
    static cudaEvent_t evA = [] {
        cudaEvent_t e; cudaEventCreateWithFlags(&e, cudaEventDisableTiming); return e;
    }();
    static cudaEvent_t evB = [] {
        cudaEvent_t e; cudaEventCreateWithFlags(&e, cudaEventDisableTiming); return e;
    }();

    // ---- main stream: init + dtype detect ----
    k_zero<<<(n + 255) / 256, 256>>>(n);
    int nq = E < 2048 ? E : 2048;
    k_detect<<<(nq + 255) / 256, 256>>>((const long long*)ei, nq);
    cudaEventRecord(evA, 0);

    // ---- side stream: CSR build (hist -> scan -> scatter), concurrent ----
    cudaStreamWaitEvent(s2, evA, 0);
    k_hist<<<(EN + 255) / 256, 256, 0, s2>>>(ei, E, EN, n);
    k_scan_block<<<nb, 1024, 0, s2>>>(n);
    k_scan_top<<<1, 128, 0, s2>>>(nb);
    k_scan_add<<<(n + 255) / 256, 256, 0, s2>>>(n, EN);
    k_scatter<<<(EN + 255) / 256, 256, 0, s2>>>(ei, E, EN, n);
    cudaEventRecord(evB, s2);

    // ---- main stream: attention scalars + accumulator clear (overlaps CSR) --
    k_wv<<<1, 128>>>(W1, as1, ad1);
    k_mv1<<<(n + 31) / 32, 256>>>(x, g_as1, g_ad1, n);
    k_zeroacc<<<480, 256>>>(n);

    // ---- join, then layer 1: GEMM with fused softmax scatter ----
    cudaStreamWaitEvent(0, evB, 0);
    k_sgemm128s<<<sgemmBlocks, 256>>>(x, W1, g_as1, g_ad1, n);

    // ---- layer 2: fused-norm SGEMM; collapsed aggregation+pool ----
    k_sgemm64f<<<sgemmBlocks, 256>>>(W2, b1, as2, ad2, g_h2, g_as2, g_ad2, n);
    k_den2<<<aggBlocks, 256>>>(g_as2, g_ad2, n);
    k_coefpool<<<POOLB, 256>>>(g_h2, g_as2, g_ad2, n);
    k_pool_b<<<1, 64>>>(b2, out, n);
}

// round 15
// speedup vs baseline: 1.2694x; 1.2694x over previous
#include <cuda_runtime.h>
#include <cuda_fp16.h>
#include <cstdint>

// ---------------- problem-size scratch (static device globals; no allocs) ---
#define NMAX 100096
#define EMAX 1600256
#define ENMAX (NMAX + EMAX)
#define POOLB 592

__device__ int    g_not64;               // 1 if edge_index is int32
__device__ int    g_deg[NMAX];
__device__ int    g_rp[NMAX + 1];        // CSR row pointers (by SRC)
__device__ int    g_cur[NMAX];
__device__ int    g_bsum[128];
__device__ int    g_sd[ENMAX];           // dst per CSR slot (src-sorted)
__device__ float  g_w[ENMAX];            // layer2 edge weights
__device__ float  g_u1[128], g_v1[128];  // W1 @ att_src1 / att_dst1
__device__ float  g_h2[NMAX * 64];       // layer2 features, row-major
__device__ float  g_as1[NMAX], g_ad1[NMAX];
__device__ float  g_as2[NMAX], g_ad2[NMAX];
__device__ float  g_acc[NMAX * 64];      // layer1 scatter accumulator
__device__ float  g_den[NMAX];           // layer1 softmax denominators
__device__ float  g_den2[NMAX];          // layer2 softmax denominators
__device__ float  g_pool[POOLB * 64];    // pool partials

// ---------------- init ------------------------------------------------------
__global__ void k_zero(int n) {
    int i = blockIdx.x * blockDim.x + threadIdx.x;
    if (i < n) g_deg[i] = 0;
    if (i == 0) g_not64 = 0;
}

// ---------------- edge-index dtype detection --------------------------------
__global__ void k_detect(const long long* __restrict__ ei, int nq) {
    int i = blockIdx.x * blockDim.x + threadIdx.x;
    if (i < nq && ((unsigned long long)ei[i] >> 32) != 0ull) atomicOr(&g_not64, 1);
}

__device__ __forceinline__ int load_idx(const void* ei, long long pos) {
    if (g_not64) return ((const int*)ei)[pos];
    return (int)((const long long*)ei)[pos];
}

__device__ __forceinline__ int clampi(int v, int n) {
    v = v < 0 ? 0 : v;
    return v >= n ? n - 1 : v;
}

// ---------------- u1 = W1 @ att_s, v1 = W1 @ att_d (1 block, 128 thr) --------
__global__ void k_wv(const float* __restrict__ Wg, const float* __restrict__ att_s,
                     const float* __restrict__ att_d) {
    __shared__ float as_[64], ad_[64];
    int t = threadIdx.x;
    if (t < 64) { as_[t] = att_s[t]; ad_[t] = att_d[t]; }
    __syncthreads();
    float u = 0.f, v = 0.f;
    const float* wr = Wg + (size_t)t * 64;
#pragma unroll 16
    for (int c = 0; c < 64; c++) { float w = wr[c]; u += w * as_[c]; v += w * ad_[c]; }
    g_u1[t] = u;
    g_v1[t] = v;
}

// ---------------- AS1/AD1 = X . u1 / X . v1 (warp per 4 rows) ----------------
__global__ void __launch_bounds__(256)
k_mv1(const float* __restrict__ X, float* __restrict__ AS, float* __restrict__ AD,
      int n) {
    __shared__ float4 us[32], vs[32];
    int tid = threadIdx.x;
    if (tid < 32) { us[tid] = ((const float4*)g_u1)[tid]; vs[tid] = ((const float4*)g_v1)[tid]; }
    __syncthreads();
    int warp = tid >> 5, lane = tid & 31;
    int r0 = (blockIdx.x * 8 + warp) * 4;
    if (r0 >= n) return;

    float4 xv[4];
#pragma unroll
    for (int rr = 0; rr < 4; rr++) {
        int row = r0 + rr < n ? r0 + rr : n - 1;
        xv[rr] = ((const float4*)(X + (size_t)row * 128))[lane];
    }
    float4 u = us[lane], v = vs[lane];
#pragma unroll
    for (int rr = 0; rr < 4; rr++) {
        float ps = xv[rr].x * u.x + xv[rr].y * u.y + xv[rr].z * u.z + xv[rr].w * u.w;
        float pd = xv[rr].x * v.x + xv[rr].y * v.y + xv[rr].z * v.z + xv[rr].w * v.w;
#pragma unroll
        for (int o = 16; o; o >>= 1) {
            ps += __shfl_xor_sync(0xffffffffu, ps, o);
            pd += __shfl_xor_sync(0xffffffffu, pd, o);
        }
        if (lane == 0 && r0 + rr < n) { AS[r0 + rr] = ps; AD[r0 + rr] = pd; }
    }
}

// ---------------- out-degree histogram (by SRC, incl. self loops) ------------
__global__ void k_hist(const void* __restrict__ ei, int E, int EN, int n) {
    int i = blockIdx.x * blockDim.x + threadIdx.x;
    if (i >= EN) return;
    int s = (i < E) ? clampi(load_idx(ei, i), n) : (i - E);
    atomicAdd(&g_deg[s], 1);
}

// ---------------- prefix scan -------------------------------------------------
__global__ void k_scan_block(int n) {
    __shared__ int s[1024];
    int i = blockIdx.x * 1024 + threadIdx.x;
    int v = (i < n) ? g_deg[i] : 0;
    s[threadIdx.x] = v;
    __syncthreads();
#pragma unroll
    for (int o = 1; o < 1024; o <<= 1) {
        int t = (threadIdx.x >= (unsigned)o) ? s[threadIdx.x - o] : 0;
        __syncthreads();
        s[threadIdx.x] += t;
        __syncthreads();
    }
    if (i < n) g_rp[i] = s[threadIdx.x] - v;
    if (threadIdx.x == 1023) g_bsum[blockIdx.x] = s[1023];
}

__global__ void k_scan_top(int nb) {
    __shared__ int s[128];
    int t = threadIdx.x;
    int v = (t < nb) ? g_bsum[t] : 0;
    s[t] = v;
    __syncthreads();
#pragma unroll
    for (int o = 1; o < 128; o <<= 1) {
        int tv = (t >= (unsigned)o) ? s[t - o] : 0;
        __syncthreads();
        s[t] += tv;
        __syncthreads();
    }
    if (t < nb) g_bsum[t] = s[t] - v;
}

__global__ void k_scan_add(int n, int total) {
    int i = blockIdx.x * blockDim.x + threadIdx.x;
    if (i < n) {
        int v = g_rp[i] + g_bsum[i >> 10];
        g_rp[i] = v;
        g_cur[i] = v;
    }
    if (i == 0) g_rp[n] = total;
}

// ---------------- scatter edges into src-CSR order (store dst) --------------
__global__ void k_scatter(const void* __restrict__ ei, int E, int EN, int n) {
    int i = blockIdx.x * blockDim.x + threadIdx.x;
    if (i >= EN) return;
    int s, d;
    if (i < E) {
        s = clampi(load_idx(ei, i), n);
        d = clampi(load_idx(ei, (long long)E + i), n);
    } else { s = i - E; d = s; }
    int pos = atomicAdd(&g_cur[s], 1);
    if (pos >= 0 && pos < ENMAX) g_sd[pos] = d;
}

// ---------------- zero accumulators ------------------------------------------
__global__ void k_zeroacc(int n) {
    int total = n * 16;   // float4 count
    float4 z = make_float4(0.f, 0.f, 0.f, 0.f);
    for (int i = blockIdx.x * blockDim.x + threadIdx.x; i < total;
         i += gridDim.x * blockDim.x) {
        ((float4*)g_acc)[i] = z;
        if (i < n) { g_den[i] = 0.f; g_den2[i] = 0.f; }
    }
}

// ---------------- red helper --------------------------------------------------
__device__ __forceinline__ void red_v4(float* p, float a, float b, float c, float d) {
    asm volatile("red.global.add.v4.f32 [%0], {%1, %2, %3, %4};"
                 :: "l"(p), "f"(a), "f"(b), "f"(c), "f"(d) : "memory");
}

// ---------------- SGEMM1 (128->64) with FUSED softmax scatter ----------------
// 64x64 tile, 4x4 micro-tiles; smem sliced to 32-k chunks (xs 8KB + ws 8KB,
// overlaid by the 64x68 epilogue out-tile) -> ~18.5KB/block, ~11 blocks/SM.
__global__ void __launch_bounds__(256)
k_sgemm128s(const float* __restrict__ X, const float* __restrict__ Wg,
            const float* __restrict__ AS, const float* __restrict__ AD, int n) {
    __shared__ float sm[64 * 68];   // compute: xs=[0,2048) ws=[2048,4096); epi: 64x68 tile
    __shared__ float sAS[64];
    __shared__ int   srp[65];

    float* xs = sm;
    float* ws = sm + 2048;

    int tid = threadIdx.x;
    int i = tid >> 4, j = tid & 15;
    int base = blockIdx.x * 64;

    if (tid < 64) sAS[tid] = AS[base + tid < n ? base + tid : n - 1];
    if (tid < 65) srp[tid] = g_rp[base + tid < n ? base + tid : n];

    float acc[4][4];
#pragma unroll
    for (int r = 0; r < 4; r++)
#pragma unroll
        for (int c = 0; c < 4; c++) acc[r][c] = 0.f;

#pragma unroll
    for (int ph = 0; ph < 4; ph++) {
        __syncthreads();
        // X slice: 64 rows x 32 k (transposed + XOR swizzled), 512 float4 tasks
#pragma unroll
        for (int t = tid; t < 512; t += 256) {
            int row = t >> 3, c4 = t & 7;
            int rc = base + row < n ? base + row : n - 1;
            float4 v = *(const float4*)(X + (size_t)rc * 128 + ph * 32 + c4 * 4);
            int g0 = row >> 2, r3 = row & 3;
#pragma unroll
            for (int s = 0; s < 4; s++) {
                int k = c4 * 4 + s;
                float val = (s == 0) ? v.x : (s == 1) ? v.y : (s == 2) ? v.z : v.w;
                xs[k * 64 + ((g0 ^ (k & 15)) << 2) + r3] = val;
            }
        }
        // W slice: 32 k x 64 cols
#pragma unroll
        for (int t = tid; t < 512; t += 256) {
            int k = t >> 4, c4 = t & 15;
            *(float4*)(ws + k * 64 + c4 * 4) =
                *(const float4*)(Wg + (size_t)(ph * 32 + k) * 64 + c4 * 4);
        }
        __syncthreads();

#pragma unroll 4
        for (int k = 0; k < 32; k++) {
            float4 a = *(const float4*)(xs + k * 64 + ((i ^ (k & 15)) << 2));
            float4 b = *(const float4*)(ws + k * 64 + j * 4);
            acc[0][0] += a.x * b.x; acc[0][1] += a.x * b.y;
            acc[0][2] += a.x * b.z; acc[0][3] += a.x * b.w;
            acc[1][0] += a.y * b.x; acc[1][1] += a.y * b.y;
            acc[1][2] += a.y * b.z; acc[1][3] += a.y * b.w;
            acc[2][0] += a.z * b.x; acc[2][1] += a.z * b.y;
            acc[2][2] += a.z * b.z; acc[2][3] += a.z * b.w;
            acc[3][0] += a.w * b.x; acc[3][1] += a.w * b.y;
            acc[3][2] += a.w * b.z; acc[3][3] += a.w * b.w;
        }
    }

    // ---- epilogue: stage out tile row-major (stride 68), then scatter ----
    __syncthreads();
#pragma unroll
    for (int rr = 0; rr < 4; rr++)
        *(float4*)(sm + (i * 4 + rr) * 68 + j * 4) =
            make_float4(acc[rr][0], acc[rr][1], acc[rr][2], acc[rr][3]);
    __syncthreads();

    int warp = tid >> 5, lane = tid & 31;
    int q = lane & 15, half = lane >> 4;
    for (int lr = warp * 8; lr < warp * 8 + 8; lr++) {
        int beg = srp[lr], end = srp[lr + 1];
        if (beg >= end) continue;
        float4 hv = *(const float4*)(sm + lr * 68 + q * 4);
        float as_v = sAS[lr];
        int jj = beg;
        for (; jj + 1 < end; jj += 2) {
            int d = g_sd[jj + half];
            float e = as_v + AD[d];
            e = (e > 0.f) ? e : 0.2f * e;
            float w = __expf(e);
            float* ap = g_acc + (size_t)d * 64 + q * 4;
            red_v4(ap, w * hv.x, w * hv.y, w * hv.z, w * hv.w);
            if (q == 0) atomicAdd(&g_den[d], w);
        }
        if (jj < end && half == 0) {
            int d = g_sd[jj];
            float e = as_v + AD[d];
            e = (e > 0.f) ? e : 0.2f * e;
            float w = __expf(e);
            float* ap = g_acc + (size_t)d * 64 + q * 4;
            red_v4(ap, w * hv.x, w * hv.y, w * hv.z, w * hv.w);
            if (q == 0) atomicAdd(&g_den[d], w);
        }
    }
}

// ---------------- SGEMM2 (64->64) with fused normalize+bias+relu on input ----
// Same 32-k sliced smem layout (xs 8KB + ws 8KB), no out-tile staging.
__global__ void __launch_bounds__(256)
k_sgemm64f(const float* __restrict__ Wg, const float* __restrict__ b1,
           const float* __restrict__ att_s, const float* __restrict__ att_d,
           float* __restrict__ H, float* __restrict__ AS, float* __restrict__ AD,
           int n) {
    __shared__ float xs[32 * 64];
    __shared__ float ws[32 * 64];
    __shared__ float atts[64], attd[64], bs[64];
    __shared__ float asd[128];

    int tid = threadIdx.x;
    int i = tid >> 4, j = tid & 15;
    int base = blockIdx.x * 64;

    if (tid < 64) { atts[tid] = att_s[tid]; attd[tid] = att_d[tid]; bs[tid] = b1[tid]; }
    if (tid < 128) asd[tid] = 0.f;

    float acc[4][4];
#pragma unroll
    for (int r = 0; r < 4; r++)
#pragma unroll
        for (int c = 0; c < 4; c++) acc[r][c] = 0.f;

#pragma unroll
    for (int ph = 0; ph < 2; ph++) {
        __syncthreads();
#pragma unroll
        for (int t = tid; t < 512; t += 256) {
            int row = t >> 3, c4 = t & 7;
            int rc = base + row < n ? base + row : n - 1;
            float inv = 1.f / (g_den[rc] + 1e-16f);
            float4 v = *(const float4*)(g_acc + (size_t)rc * 64 + ph * 32 + c4 * 4);
            int g0 = row >> 2, r3 = row & 3;
#pragma unroll
            for (int s = 0; s < 4; s++) {
                int k = c4 * 4 + s;
                float val = (s == 0) ? v.x : (s == 1) ? v.y : (s == 2) ? v.z : v.w;
                val = fmaxf(val * inv + bs[ph * 32 + k], 0.f);
                xs[k * 64 + ((g0 ^ (k & 15)) << 2) + r3] = val;
            }
        }
#pragma unroll
        for (int t = tid; t < 512; t += 256) {
            int k = t >> 4, c4 = t & 15;
            *(float4*)(ws + k * 64 + c4 * 4) =
                *(const float4*)(Wg + (size_t)(ph * 32 + k) * 64 + c4 * 4);
        }
        __syncthreads();

#pragma unroll 4
        for (int k = 0; k < 32; k++) {
            float4 a = *(const float4*)(xs + k * 64 + ((i ^ (k & 15)) << 2));
            float4 b = *(const float4*)(ws + k * 64 + j * 4);
            acc[0][0] += a.x * b.x; acc[0][1] += a.x * b.y;
            acc[0][2] += a.x * b.z; acc[0][3] += a.x * b.w;
            acc[1][0] += a.y * b.x; acc[1][1] += a.y * b.y;
            acc[1][2] += a.y * b.z; acc[1][3] += a.y * b.w;
            acc[2][0] += a.z * b.x; acc[2][1] += a.z * b.y;
            acc[2][2] += a.z * b.z; acc[2][3] += a.z * b.w;
            acc[3][0] += a.w * b.x; acc[3][1] += a.w * b.y;
            acc[3][2] += a.w * b.z; acc[3][3] += a.w * b.w;
        }
    }

#pragma unroll
    for (int rr = 0; rr < 4; rr++) {
        int row = base + i * 4 + rr;
        if (row < n) {
            float4 o = make_float4(acc[rr][0], acc[rr][1], acc[rr][2], acc[rr][3]);
            *(float4*)(H + (size_t)row * 64 + j * 4) = o;
            float ps = acc[rr][0] * atts[j * 4] + acc[rr][1] * atts[j * 4 + 1]
                     + acc[rr][2] * atts[j * 4 + 2] + acc[rr][3] * atts[j * 4 + 3];
            float pd = acc[rr][0] * attd[j * 4] + acc[rr][1] * attd[j * 4 + 1]
                     + acc[rr][2] * attd[j * 4 + 2] + acc[rr][3] * attd[j * 4 + 3];
            atomicAdd(&asd[i * 4 + rr], ps);
            atomicAdd(&asd[64 + i * 4 + rr], pd);
        }
    }
    __syncthreads();
    if (tid < 64 && base + tid < n) {
        AS[base + tid] = asd[tid];
        AD[base + tid] = asd[64 + tid];
    }
}

// ---------------- layer-2 denominators + edge weights (warp per SRC) ---------
__global__ void __launch_bounds__(256)
k_den2(const float* __restrict__ AS, const float* __restrict__ AD, int n) {
    int src = (blockIdx.x * blockDim.x + threadIdx.x) >> 5;
    int lane = threadIdx.x & 31;
    if (src >= n) return;
    float as_v = AS[src];
    int beg = g_rp[src], end = g_rp[src + 1];
    for (int j = beg + lane; j < end; j += 32) {
        int d = g_sd[j];
        float e = as_v + AD[d];
        e = (e > 0.f) ? e : 0.2f * e;
        float w = __expf(e);
        g_w[j] = w;
        atomicAdd(&g_den2[d], w);
    }
}

// ---------------- layer-2 collapsed aggregation+pool: warp per SRC -----------
__global__ void __launch_bounds__(256)
k_coefpool(const float* __restrict__ H2, int n) {
    __shared__ float sm[8][64];
    int warp = threadIdx.x >> 5, lane = threadIdx.x & 31;
    int gw = blockIdx.x * 8 + warp;
    int stride = gridDim.x * 8;

    float acc0 = 0.f, acc1 = 0.f;
    for (int src = gw; src < n; src += stride) {
        int beg = g_rp[src], end = g_rp[src + 1];
        float a = 0.f;
        for (int j = beg + lane; j < end; j += 32)
            a += g_w[j] / (g_den2[g_sd[j]] + 1e-16f);
#pragma unroll
        for (int o = 16; o; o >>= 1) a += __shfl_xor_sync(0xffffffffu, a, o);
        const float* hp = H2 + (size_t)src * 64;
        acc0 += a * hp[lane];
        acc1 += a * hp[lane + 32];
    }
    sm[warp][lane] = acc0;
    sm[warp][lane + 32] = acc1;
    __syncthreads();
    if (threadIdx.x < 64) {
        float v = 0.f;
#pragma unroll
        for (int w = 0; w < 8; w++) v += sm[w][threadIdx.x];
        g_pool[blockIdx.x * 64 + threadIdx.x] = v;
    }
}

// ---------------- final reduce + bias ----------------------------------------
__global__ void k_pool_b(const float* __restrict__ b2, float* __restrict__ out,
                         int n) {
    int col = threadIdx.x;   // 64 threads
    float acc = 0.f;
    for (int b = 0; b < POOLB; b++) acc += g_pool[b * 64 + col];
    out[col] = acc * (1.0f / (float)n) + b2[col];
}

// ---------------- launch ----------------------------------------------------
extern "C" void kernel_launch(void* const* d_in, const int* in_sizes, int n_in,
                              void* d_out, int out_size) {
    const float* x   = (const float*)d_in[0];
    const void*  ei  = d_in[1];
    const float* W1  = (const float*)d_in[3];
    const float* as1 = (const float*)d_in[4];
    const float* ad1 = (const float*)d_in[5];
    const float* b1  = (const float*)d_in[6];
    const float* W2  = (const float*)d_in[7];
    const float* as2 = (const float*)d_in[8];
    const float* ad2 = (const float*)d_in[9];
    const float* b2  = (const float*)d_in[10];
    float* out = (float*)d_out;

    int n  = in_sizes[0] / 128;   // N nodes
    int E  = in_sizes[1] / 2;     // edges
    int EN = E + n;               // edges + self loops

    int sgemmBlocks = (n + 63) / 64;
    int aggBlocks   = (n + 7) / 8;
    int nb          = (n + 1023) / 1024;

    k_zero<<<(n + 255) / 256, 256>>>(n);
    int nq = E < 2048 ? E : 2048;
    k_detect<<<(nq + 255) / 256, 256>>>((const long long*)ei, nq);
    k_wv<<<1, 128>>>(W1, as1, ad1);
    k_mv1<<<(n + 31) / 32, 256>>>(x, g_as1, g_ad1, n);
    k_hist<<<(EN + 255) / 256, 256>>>(ei, E, EN, n);
    k_scan_block<<<nb, 1024>>>(n);
    k_scan_top<<<1, 128>>>(nb);
    k_scan_add<<<(n + 255) / 256, 256>>>(n, EN);
    k_scatter<<<(EN + 255) / 256, 256>>>(ei, E, EN, n);
    k_zeroacc<<<480, 256>>>(n);

    // --- layer 1: GEMM with fused softmax scatter ---
    k_sgemm128s<<<sgemmBlocks, 256>>>(x, W1, g_as1, g_ad1, n);

    // --- layer 2: fused-norm SGEMM; collapsed aggregation+pool ---
    k_sgemm64f<<<sgemmBlocks, 256>>>(W2, b1, as2, ad2, g_h2, g_as2, g_ad2, n);
    k_den2<<<aggBlocks, 256>>>(g_as2, g_ad2, n);
    k_coefpool<<<POOLB, 256>>>(g_h2, n);
    k_pool_b<<<1, 64>>>(b2, out, n);
}

// round 16
// speedup vs baseline: 1.2781x; 1.0069x over previous
#include <cuda_runtime.h>
#include <cuda_fp16.h>
#include <cstdint>

// ---------------- problem-size scratch (static device globals; no allocs) ---
#define NMAX 100096
#define EMAX 1600256
#define ENMAX (NMAX + EMAX)
#define POOLB 592

__device__ int    g_not64;               // 1 if edge_index is int32
__device__ int    g_deg[NMAX];
__device__ int    g_rp[NMAX + 1];        // CSR row pointers (by SRC)
__device__ int    g_cur[NMAX];
__device__ int    g_bsum[128];
__device__ int    g_sd[ENMAX];           // dst per CSR slot (src-sorted)
__device__ float  g_w[ENMAX];            // layer2 edge weights
__device__ float  g_u1[128], g_v1[128];  // W1 @ att_src1 / att_dst1
__device__ float  g_h2[NMAX * 64];       // layer2 features, row-major
__device__ float  g_as1[NMAX], g_ad1[NMAX];
__device__ float  g_as2[NMAX], g_ad2[NMAX];
__device__ float  g_acc[NMAX * 64];      // layer1 scatter accumulator
__device__ float  g_den[NMAX];           // layer1 softmax denominators
__device__ float  g_den2[NMAX];          // layer2 softmax denominators
__device__ float  g_pool[POOLB * 64];    // pool partials

// ---------------- init ------------------------------------------------------
__global__ void k_zero(int n) {
    int i = blockIdx.x * blockDim.x + threadIdx.x;
    if (i < n) g_deg[i] = 0;
    if (i == 0) g_not64 = 0;
}

// ---------------- edge-index dtype detection --------------------------------
__global__ void k_detect(const long long* __restrict__ ei, int nq) {
    int i = blockIdx.x * blockDim.x + threadIdx.x;
    if (i < nq && ((unsigned long long)ei[i] >> 32) != 0ull) atomicOr(&g_not64, 1);
}

__device__ __forceinline__ int load_idx(const void* ei, long long pos) {
    if (g_not64) return ((const int*)ei)[pos];
    return (int)((const long long*)ei)[pos];
}

__device__ __forceinline__ int clampi(int v, int n) {
    v = v < 0 ? 0 : v;
    return v >= n ? n - 1 : v;
}

// ---------------- u1 = W1 @ att_s, v1 = W1 @ att_d (1 block, 128 thr) --------
__global__ void k_wv(const float* __restrict__ Wg, const float* __restrict__ att_s,
                     const float* __restrict__ att_d) {
    __shared__ float as_[64], ad_[64];
    int t = threadIdx.x;
    if (t < 64) { as_[t] = att_s[t]; ad_[t] = att_d[t]; }
    __syncthreads();
    float u = 0.f, v = 0.f;
    const float* wr = Wg + (size_t)t * 64;
#pragma unroll 16
    for (int c = 0; c < 64; c++) { float w = wr[c]; u += w * as_[c]; v += w * ad_[c]; }
    g_u1[t] = u;
    g_v1[t] = v;
}

// ---------------- AS1/AD1 = X . u1 / X . v1 (warp per 4 rows) ----------------
__global__ void __launch_bounds__(256)
k_mv1(const float* __restrict__ X, float* __restrict__ AS, float* __restrict__ AD,
      int n) {
    __shared__ float4 us[32], vs[32];
    int tid = threadIdx.x;
    if (tid < 32) { us[tid] = ((const float4*)g_u1)[tid]; vs[tid] = ((const float4*)g_v1)[tid]; }
    __syncthreads();
    int warp = tid >> 5, lane = tid & 31;
    int r0 = (blockIdx.x * 8 + warp) * 4;
    if (r0 >= n) return;

    float4 xv[4];
#pragma unroll
    for (int rr = 0; rr < 4; rr++) {
        int row = r0 + rr < n ? r0 + rr : n - 1;
        xv[rr] = ((const float4*)(X + (size_t)row * 128))[lane];
    }
    float4 u = us[lane], v = vs[lane];
#pragma unroll
    for (int rr = 0; rr < 4; rr++) {
        float ps = xv[rr].x * u.x + xv[rr].y * u.y + xv[rr].z * u.z + xv[rr].w * u.w;
        float pd = xv[rr].x * v.x + xv[rr].y * v.y + xv[rr].z * v.z + xv[rr].w * v.w;
#pragma unroll
        for (int o = 16; o; o >>= 1) {
            ps += __shfl_xor_sync(0xffffffffu, ps, o);
            pd += __shfl_xor_sync(0xffffffffu, pd, o);
        }
        if (lane == 0 && r0 + rr < n) { AS[r0 + rr] = ps; AD[r0 + rr] = pd; }
    }
}

// ---------------- out-degree histogram (by SRC, incl. self loops) ------------
__global__ void k_hist(const void* __restrict__ ei, int E, int EN, int n) {
    int i = blockIdx.x * blockDim.x + threadIdx.x;
    if (i >= EN) return;
    int s = (i < E) ? clampi(load_idx(ei, i), n) : (i - E);
    atomicAdd(&g_deg[s], 1);
}

// ---------------- prefix scan -------------------------------------------------
__global__ void k_scan_block(int n) {
    __shared__ int s[1024];
    int i = blockIdx.x * 1024 + threadIdx.x;
    int v = (i < n) ? g_deg[i] : 0;
    s[threadIdx.x] = v;
    __syncthreads();
#pragma unroll
    for (int o = 1; o < 1024; o <<= 1) {
        int t = (threadIdx.x >= (unsigned)o) ? s[threadIdx.x - o] : 0;
        __syncthreads();
        s[threadIdx.x] += t;
        __syncthreads();
    }
    if (i < n) g_rp[i] = s[threadIdx.x] - v;
    if (threadIdx.x == 1023) g_bsum[blockIdx.x] = s[1023];
}

__global__ void k_scan_top(int nb) {
    __shared__ int s[128];
    int t = threadIdx.x;
    int v = (t < nb) ? g_bsum[t] : 0;
    s[t] = v;
    __syncthreads();
#pragma unroll
    for (int o = 1; o < 128; o <<= 1) {
        int tv = (t >= (unsigned)o) ? s[t - o] : 0;
        __syncthreads();
        s[t] += tv;
        __syncthreads();
    }
    if (t < nb) g_bsum[t] = s[t] - v;
}

__global__ void k_scan_add(int n, int total) {
    int i = blockIdx.x * blockDim.x + threadIdx.x;
    if (i < n) {
        int v = g_rp[i] + g_bsum[i >> 10];
        g_rp[i] = v;
        g_cur[i] = v;
    }
    if (i == 0) g_rp[n] = total;
}

// ---------------- scatter edges into src-CSR order (store dst) --------------
__global__ void k_scatter(const void* __restrict__ ei, int E, int EN, int n) {
    int i = blockIdx.x * blockDim.x + threadIdx.x;
    if (i >= EN) return;
    int s, d;
    if (i < E) {
        s = clampi(load_idx(ei, i), n);
        d = clampi(load_idx(ei, (long long)E + i), n);
    } else { s = i - E; d = s; }
    int pos = atomicAdd(&g_cur[s], 1);
    if (pos >= 0 && pos < ENMAX) g_sd[pos] = d;
}

// ---------------- zero accumulators ------------------------------------------
__global__ void k_zeroacc(int n) {
    int total = n * 16;   // float4 count
    float4 z = make_float4(0.f, 0.f, 0.f, 0.f);
    for (int i = blockIdx.x * blockDim.x + threadIdx.x; i < total;
         i += gridDim.x * blockDim.x) {
        ((float4*)g_acc)[i] = z;
        if (i < n) { g_den[i] = 0.f; g_den2[i] = 0.f; }
    }
}

// ---------------- red helper --------------------------------------------------
__device__ __forceinline__ void red_v4(float* p, float a, float b, float c, float d) {
    asm volatile("red.global.add.v4.f32 [%0], {%1, %2, %3, %4};"
                 :: "l"(p), "f"(a), "f"(b), "f"(c), "f"(d) : "memory");
}

// ---------------- SGEMM1 (128->64) with FUSED softmax scatter ----------------
// R13 layout (measured 948us); epilogue now quarter-warp per edge: 4 edges in
// flight per loop iteration (2x MLP on AD gather + atomic stream).
__global__ void __launch_bounds__(256)
k_sgemm128s(const float* __restrict__ X, const float* __restrict__ Wg,
            const float* __restrict__ AS, const float* __restrict__ AD, int n) {
    __shared__ float xs[64 * 68];   // staging (stride 64 + XOR) then out tile (stride 68)
    __shared__ float ws[64 * 64];
    __shared__ float sAS[64];
    __shared__ int   srp[65];

    int tid = threadIdx.x;
    int i = tid >> 4, j = tid & 15;
    int base = blockIdx.x * 64;

    if (tid < 64) sAS[tid] = AS[base + tid < n ? base + tid : n - 1];
    if (tid < 65) srp[tid] = g_rp[base + tid < n ? base + tid : n];

    float acc[4][4];
#pragma unroll
    for (int r = 0; r < 4; r++)
#pragma unroll
        for (int c = 0; c < 4; c++) acc[r][c] = 0.f;

#pragma unroll
    for (int ph = 0; ph < 2; ph++) {
        __syncthreads();
#pragma unroll
        for (int t = tid; t < 1024; t += 256) {
            int row = t >> 4, c4 = t & 15;
            int rc = base + row < n ? base + row : n - 1;
            float4 v = *(const float4*)(X + (size_t)rc * 128 + ph * 64 + c4 * 4);
            int g0 = row >> 2, r3 = row & 3;
#pragma unroll
            for (int s = 0; s < 4; s++) {
                int k = c4 * 4 + s;
                float val = (s == 0) ? v.x : (s == 1) ? v.y : (s == 2) ? v.z : v.w;
                xs[k * 64 + ((g0 ^ (k & 15)) << 2) + r3] = val;
            }
        }
#pragma unroll
        for (int t = tid; t < 1024; t += 256) {
            int k = t >> 4, c4 = t & 15;
            *(float4*)(ws + k * 64 + c4 * 4) =
                *(const float4*)(Wg + (size_t)(ph * 64 + k) * 64 + c4 * 4);
        }
        __syncthreads();

#pragma unroll 4
        for (int k = 0; k < 64; k++) {
            float4 a = *(const float4*)(xs + k * 64 + ((i ^ (k & 15)) << 2));
            float4 b = *(const float4*)(ws + k * 64 + j * 4);
            acc[0][0] += a.x * b.x; acc[0][1] += a.x * b.y;
            acc[0][2] += a.x * b.z; acc[0][3] += a.x * b.w;
            acc[1][0] += a.y * b.x; acc[1][1] += a.y * b.y;
            acc[1][2] += a.y * b.z; acc[1][3] += a.y * b.w;
            acc[2][0] += a.z * b.x; acc[2][1] += a.z * b.y;
            acc[2][2] += a.z * b.z; acc[2][3] += a.z * b.w;
            acc[3][0] += a.w * b.x; acc[3][1] += a.w * b.y;
            acc[3][2] += a.w * b.z; acc[3][3] += a.w * b.w;
        }
    }

    // ---- epilogue: stage out tile row-major (stride 68), then scatter ----
    __syncthreads();
#pragma unroll
    for (int rr = 0; rr < 4; rr++)
        *(float4*)(xs + (i * 4 + rr) * 68 + j * 4) =
            make_float4(acc[rr][0], acc[rr][1], acc[rr][2], acc[rr][3]);
    __syncthreads();

    int warp = tid >> 5, lane = tid & 31;
    int q = lane & 7;          // column group 0..7 (8 floats each)
    int sub = lane >> 3;       // 0..3: edge within quad
    for (int lr = warp * 8; lr < warp * 8 + 8; lr++) {
        int beg = srp[lr], end = srp[lr + 1];
        if (beg >= end) continue;
        float4 h0 = *(const float4*)(xs + lr * 68 + q * 8);
        float4 h1 = *(const float4*)(xs + lr * 68 + q * 8 + 4);
        float as_v = sAS[lr];
        for (int jj = beg; jj < end; jj += 4) {
            int idx = jj + sub;
            bool act = idx < end;
            int d = act ? g_sd[idx] : 0;
            float e = as_v + AD[d];
            e = (e > 0.f) ? e : 0.2f * e;
            float w = __expf(e);
            if (act) {
                float* ap = g_acc + (size_t)d * 64 + q * 8;
                red_v4(ap,     w * h0.x, w * h0.y, w * h0.z, w * h0.w);
                red_v4(ap + 4, w * h1.x, w * h1.y, w * h1.z, w * h1.w);
                if (q == 0) atomicAdd(&g_den[d], w);
            }
        }
    }
}

// ---------------- SGEMM2 (64->64) with fused normalize+bias+relu on input ----
__global__ void __launch_bounds__(256)
k_sgemm64f(const float* __restrict__ Wg, const float* __restrict__ b1,
           const float* __restrict__ att_s, const float* __restrict__ att_d,
           float* __restrict__ H, float* __restrict__ AS, float* __restrict__ AD,
           int n) {
    __shared__ float xs[64 * 64];
    __shared__ float ws[64 * 64];
    __shared__ float atts[64], attd[64], bs[64];
    __shared__ float asd[128];

    int tid = threadIdx.x;
    int i = tid >> 4, j = tid & 15;
    int base = blockIdx.x * 64;

    if (tid < 64) { atts[tid] = att_s[tid]; attd[tid] = att_d[tid]; bs[tid] = b1[tid]; }
    if (tid < 128) asd[tid] = 0.f;
    __syncthreads();

#pragma unroll
    for (int t = tid; t < 1024; t += 256) {
        int row = t >> 4, c4 = t & 15;
        int rc = base + row < n ? base + row : n - 1;
        float inv = 1.f / (g_den[rc] + 1e-16f);
        float4 v = *(const float4*)(g_acc + (size_t)rc * 64 + c4 * 4);
        int g0 = row >> 2, r3 = row & 3;
#pragma unroll
        for (int s = 0; s < 4; s++) {
            int k = c4 * 4 + s;
            float val = (s == 0) ? v.x : (s == 1) ? v.y : (s == 2) ? v.z : v.w;
            val = fmaxf(val * inv + bs[k], 0.f);
            xs[k * 64 + ((g0 ^ (k & 15)) << 2) + r3] = val;
        }
    }
#pragma unroll
    for (int t = tid; t < 1024; t += 256) {
        int k = t >> 4, c4 = t & 15;
        *(float4*)(ws + k * 64 + c4 * 4) =
            *(const float4*)(Wg + (size_t)k * 64 + c4 * 4);
    }
    __syncthreads();

    float acc[4][4];
#pragma unroll
    for (int r = 0; r < 4; r++)
#pragma unroll
        for (int c = 0; c < 4; c++) acc[r][c] = 0.f;

#pragma unroll 4
    for (int k = 0; k < 64; k++) {
        float4 a = *(const float4*)(xs + k * 64 + ((i ^ (k & 15)) << 2));
        float4 b = *(const float4*)(ws + k * 64 + j * 4);
        acc[0][0] += a.x * b.x; acc[0][1] += a.x * b.y;
        acc[0][2] += a.x * b.z; acc[0][3] += a.x * b.w;
        acc[1][0] += a.y * b.x; acc[1][1] += a.y * b.y;
        acc[1][2] += a.y * b.z; acc[1][3] += a.y * b.w;
        acc[2][0] += a.z * b.x; acc[2][1] += a.z * b.y;
        acc[2][2] += a.z * b.z; acc[2][3] += a.z * b.w;
        acc[3][0] += a.w * b.x; acc[3][1] += a.w * b.y;
        acc[3][2] += a.w * b.z; acc[3][3] += a.w * b.w;
    }

#pragma unroll
    for (int rr = 0; rr < 4; rr++) {
        int row = base + i * 4 + rr;
        if (row < n) {
            float4 o = make_float4(acc[rr][0], acc[rr][1], acc[rr][2], acc[rr][3]);
            *(float4*)(H + (size_t)row * 64 + j * 4) = o;
            float ps = acc[rr][0] * atts[j * 4] + acc[rr][1] * atts[j * 4 + 1]
                     + acc[rr][2] * atts[j * 4 + 2] + acc[rr][3] * atts[j * 4 + 3];
            float pd = acc[rr][0] * attd[j * 4] + acc[rr][1] * attd[j * 4 + 1]
                     + acc[rr][2] * attd[j * 4 + 2] + acc[rr][3] * attd[j * 4 + 3];
            atomicAdd(&asd[i * 4 + rr], ps);
            atomicAdd(&asd[64 + i * 4 + rr], pd);
        }
    }
    __syncthreads();
    if (tid < 64 && base + tid < n) {
        AS[base + tid] = asd[tid];
        AD[base + tid] = asd[64 + tid];
    }
}

// ---------------- layer-2 denominators + edge weights (warp per SRC) ---------
__global__ void __launch_bounds__(256)
k_den2(const float* __restrict__ AS, const float* __restrict__ AD, int n) {
    int src = (blockIdx.x * blockDim.x + threadIdx.x) >> 5;
    int lane = threadIdx.x & 31;
    if (src >= n) return;
    float as_v = AS[src];
    int beg = g_rp[src], end = g_rp[src + 1];
    for (int j = beg + lane; j < end; j += 32) {
        int d = g_sd[j];
        float e = as_v + AD[d];
        e = (e > 0.f) ? e : 0.2f * e;
        float w = __expf(e);
        g_w[j] = w;
        atomicAdd(&g_den2[d], w);
    }
}

// ---------------- layer-2 collapsed aggregation+pool: warp per SRC -----------
__global__ void __launch_bounds__(256)
k_coefpool(const float* __restrict__ H2, int n) {
    __shared__ float sm[8][64];
    int warp = threadIdx.x >> 5, lane = threadIdx.x & 31;
    int gw = blockIdx.x * 8 + warp;
    int stride = gridDim.x * 8;

    float acc0 = 0.f, acc1 = 0.f;
    for (int src = gw; src < n; src += stride) {
        int beg = g_rp[src], end = g_rp[src + 1];
        float a = 0.f;
        for (int j = beg + lane; j < end; j += 32)
            a += g_w[j] / (g_den2[g_sd[j]] + 1e-16f);
#pragma unroll
        for (int o = 16; o; o >>= 1) a += __shfl_xor_sync(0xffffffffu, a, o);
        const float* hp = H2 + (size_t)src * 64;
        acc0 += a * hp[lane];
        acc1 += a * hp[lane + 32];
    }
    sm[warp][lane] = acc0;
    sm[warp][lane + 32] = acc1;
    __syncthreads();
    if (threadIdx.x < 64) {
        float v = 0.f;
#pragma unroll
        for (int w = 0; w < 8; w++) v += sm[w][threadIdx.x];
        g_pool[blockIdx.x * 64 + threadIdx.x] = v;
    }
}

// ---------------- final reduce + bias ----------------------------------------
__global__ void k_pool_b(const float* __restrict__ b2, float* __restrict__ out,
                         int n) {
    int col = threadIdx.x;   // 64 threads
    float acc = 0.f;
    for (int b = 0; b < POOLB; b++) acc += g_pool[b * 64 + col];
    out[col] = acc * (1.0f / (float)n) + b2[col];
}

// ---------------- launch ----------------------------------------------------
extern "C" void kernel_launch(void* const* d_in, const int* in_sizes, int n_in,
                              void* d_out, int out_size) {
    const float* x   = (const float*)d_in[0];
    const void*  ei  = d_in[1];
    const float* W1  = (const float*)d_in[3];
    const float* as1 = (const float*)d_in[4];
    const float* ad1 = (const float*)d_in[5];
    const float* b1  = (const float*)d_in[6];
    const float* W2  = (const float*)d_in[7];
    const float* as2 = (const float*)d_in[8];
    const float* ad2 = (const float*)d_in[9];
    const float* b2  = (const float*)d_in[10];
    float* out = (float*)d_out;

    int n  = in_sizes[0] / 128;   // N nodes
    int E  = in_sizes[1] / 2;     // edges
    int EN = E + n;               // edges + self loops

    int sgemmBlocks = (n + 63) / 64;
    int aggBlocks   = (n + 7) / 8;
    int nb          = (n + 1023) / 1024;

    k_zero<<<(n + 255) / 256, 256>>>(n);
    int nq = E < 2048 ? E : 2048;
    k_detect<<<(nq + 255) / 256, 256>>>((const long long*)ei, nq);
    k_wv<<<1, 128>>>(W1, as1, ad1);
    k_mv1<<<(n + 31) / 32, 256>>>(x, g_as1, g_ad1, n);
    k_hist<<<(EN + 255) / 256, 256>>>(ei, E, EN, n);
    k_scan_block<<<nb, 1024>>>(n);
    k_scan_top<<<1, 128>>>(nb);
    k_scan_add<<<(n + 255) / 256, 256>>>(n, EN);
    k_scatter<<<(EN + 255) / 256, 256>>>(ei, E, EN, n);
    k_zeroacc<<<480, 256>>>(n);

    // --- layer 1: GEMM with fused softmax scatter (quad-edge epilogue) ---
    k_sgemm128s<<<sgemmBlocks, 256>>>(x, W1, g_as1, g_ad1, n);

    // --- layer 2: fused-norm SGEMM; collapsed aggregation+pool ---
    k_sgemm64f<<<sgemmBlocks, 256>>>(W2, b1, as2, ad2, g_h2, g_as2, g_ad2, n);
    k_den2<<<aggBlocks, 256>>>(g_as2, g_ad2, n);
    k_coefpool<<<POOLB, 256>>>(g_h2, n);
    k_pool_b<<<1, 64>>>(b2, out, n);
}

// round 17
// speedup vs baseline: 3.9037x; 3.0544x over previous
#include <cuda_runtime.h>
#include <cuda_fp16.h>
#include <cstdint>

// ---------------- problem-size scratch (static device globals; no allocs) ---
#define NMAX 100096
#define EMAX 1600256
#define ENMAX (NMAX + EMAX)
#define POOLB 1600

__device__ int    g_not64;               // 1 if edge_index is int32
__device__ int    g_deg[NMAX];
__device__ int    g_rp[NMAX + 1];        // CSR row pointers (by SRC)
__device__ int    g_cur[NMAX];
__device__ int    g_bsum[128];
__device__ int    g_sd[ENMAX];           // dst per CSR slot (src-sorted)
__device__ float  g_w[ENMAX];            // layer2 edge weights
__device__ float  g_u1[128], g_v1[128];  // W1 @ att_src1 / att_dst1 (128-dim)
__device__ float  g_u2[64],  g_v2[64];   // W2 @ att_src2 / att_dst2 (64-dim)
__device__ float  g_as1[NMAX], g_ad1[NMAX];
__device__ float  g_as2[NMAX], g_ad2[NMAX];
__device__ float  g_acc[NMAX * 64];      // layer1 scatter accumulator
__device__ float  g_den[NMAX];           // layer1 softmax denominators
__device__ float  g_den2[NMAX];          // layer2 softmax denominators
__device__ float  g_pool[POOLB * 64];    // pool partials (per layer-2 block)

// ---------------- init ------------------------------------------------------
__global__ void k_zero(int n) {
    int i = blockIdx.x * blockDim.x + threadIdx.x;
    if (i < n) g_deg[i] = 0;
    if (i == 0) g_not64 = 0;
}

// ---------------- edge-index dtype detection --------------------------------
__global__ void k_detect(const long long* __restrict__ ei, int nq) {
    int i = blockIdx.x * blockDim.x + threadIdx.x;
    if (i < nq && ((unsigned long long)ei[i] >> 32) != 0ull) atomicOr(&g_not64, 1);
}

__device__ __forceinline__ int load_idx(const void* ei, long long pos) {
    if (g_not64) return ((const int*)ei)[pos];
    return (int)((const long long*)ei)[pos];
}

__device__ __forceinline__ int clampi(int v, int n) {
    v = v < 0 ? 0 : v;
    return v >= n ? n - 1 : v;
}

// ---------------- u1 = W1 @ att_s1, v1 = W1 @ att_d1 (128 threads) -----------
__global__ void k_wv1(const float* __restrict__ Wg, const float* __restrict__ att_s,
                      const float* __restrict__ att_d) {
    __shared__ float as_[64], ad_[64];
    int t = threadIdx.x;
    if (t < 64) { as_[t] = att_s[t]; ad_[t] = att_d[t]; }
    __syncthreads();
    float u = 0.f, v = 0.f;
    const float* wr = Wg + (size_t)t * 64;
#pragma unroll 16
    for (int c = 0; c < 64; c++) { float w = wr[c]; u += w * as_[c]; v += w * ad_[c]; }
    g_u1[t] = u;
    g_v1[t] = v;
}

// ---------------- u2 = W2 @ att_s2, v2 = W2 @ att_d2 (64 threads) ------------
__global__ void k_wv2(const float* __restrict__ Wg, const float* __restrict__ att_s,
                      const float* __restrict__ att_d) {
    __shared__ float as_[64], ad_[64];
    int t = threadIdx.x;
    as_[t] = att_s[t]; ad_[t] = att_d[t];
    __syncthreads();
    float u = 0.f, v = 0.f;
    const float* wr = Wg + (size_t)t * 64;
#pragma unroll 16
    for (int c = 0; c < 64; c++) { float w = wr[c]; u += w * as_[c]; v += w * ad_[c]; }
    g_u2[t] = u;
    g_v2[t] = v;
}

// ---------------- AS1/AD1 = X . u1 / X . v1 (warp per 4 rows, 128-dim) -------
__global__ void __launch_bounds__(256)
k_mv1(const float* __restrict__ X, int n) {
    __shared__ float4 us[32], vs[32];
    int tid = threadIdx.x;
    if (tid < 32) { us[tid] = ((const float4*)g_u1)[tid]; vs[tid] = ((const float4*)g_v1)[tid]; }
    __syncthreads();
    int warp = tid >> 5, lane = tid & 31;
    int r0 = (blockIdx.x * 8 + warp) * 4;
    if (r0 >= n) return;

    float4 xv[4];
#pragma unroll
    for (int rr = 0; rr < 4; rr++) {
        int row = r0 + rr < n ? r0 + rr : n - 1;
        xv[rr] = ((const float4*)(X + (size_t)row * 128))[lane];
    }
    float4 u = us[lane], v = vs[lane];
#pragma unroll
    for (int rr = 0; rr < 4; rr++) {
        float ps = xv[rr].x * u.x + xv[rr].y * u.y + xv[rr].z * u.z + xv[rr].w * u.w;
        float pd = xv[rr].x * v.x + xv[rr].y * v.y + xv[rr].z * v.z + xv[rr].w * v.w;
#pragma unroll
        for (int o = 16; o; o >>= 1) {
            ps += __shfl_xor_sync(0xffffffffu, ps, o);
            pd += __shfl_xor_sync(0xffffffffu, pd, o);
        }
        if (lane == 0 && r0 + rr < n) { g_as1[r0 + rr] = ps; g_ad1[r0 + rr] = pd; }
    }
}

// ---------------- AS2/AD2 from normalized acc rows (warp per 8 rows) ---------
// xt = relu(acc/den1 + b1); AS2 = xt.u2, AD2 = xt.v2. Streams acc once.
__global__ void __launch_bounds__(256)
k_mv2(const float* __restrict__ b1, int n) {
    __shared__ float2 us[32], vs[32], bsl[32];
    int tid = threadIdx.x;
    if (tid < 32) {
        us[tid] = ((const float2*)g_u2)[tid];
        vs[tid] = ((const float2*)g_v2)[tid];
        bsl[tid] = ((const float2*)b1)[tid];
    }
    __syncthreads();
    int warp = tid >> 5, lane = tid & 31;
    int r0 = (blockIdx.x * 8 + warp) * 8;
    if (r0 >= n) return;
    float2 u = us[lane], v = vs[lane], bb = bsl[lane];

#pragma unroll
    for (int rr = 0; rr < 8; rr++) {
        int row = r0 + rr;
        if (row >= n) break;
        float inv = 1.f / (g_den[row] + 1e-16f);
        float2 av = ((const float2*)(g_acc + (size_t)row * 64))[lane];
        float x0 = fmaxf(av.x * inv + bb.x, 0.f);
        float x1 = fmaxf(av.y * inv + bb.y, 0.f);
        float ps = x0 * u.x + x1 * u.y;
        float pd = x0 * v.x + x1 * v.y;
#pragma unroll
        for (int o = 16; o; o >>= 1) {
            ps += __shfl_xor_sync(0xffffffffu, ps, o);
            pd += __shfl_xor_sync(0xffffffffu, pd, o);
        }
        if (lane == 0) { g_as2[row] = ps; g_ad2[row] = pd; }
    }
}

// ---------------- out-degree histogram (by SRC, incl. self loops) ------------
__global__ void k_hist(const void* __restrict__ ei, int E, int EN, int n) {
    int i = blockIdx.x * blockDim.x + threadIdx.x;
    if (i >= EN) return;
    int s = (i < E) ? clampi(load_idx(ei, i), n) : (i - E);
    atomicAdd(&g_deg[s], 1);
}

// ---------------- prefix scan -------------------------------------------------
__global__ void k_scan_block(int n) {
    __shared__ int s[1024];
    int i = blockIdx.x * 1024 + threadIdx.x;
    int v = (i < n) ? g_deg[i] : 0;
    s[threadIdx.x] = v;
    __syncthreads();
#pragma unroll
    for (int o = 1; o < 1024; o <<= 1) {
        int t = (threadIdx.x >= (unsigned)o) ? s[threadIdx.x - o] : 0;
        __syncthreads();
        s[threadIdx.x] += t;
        __syncthreads();
    }
    if (i < n) g_rp[i] = s[threadIdx.x] - v;
    if (threadIdx.x == 1023) g_bsum[blockIdx.x] = s[1023];
}

__global__ void k_scan_top(int nb) {
    __shared__ int s[128];
    int t = threadIdx.x;
    int v = (t < nb) ? g_bsum[t] : 0;
    s[t] = v;
    __syncthreads();
#pragma unroll
    for (int o = 1; o < 128; o <<= 1) {
        int tv = (t >= (unsigned)o) ? s[t - o] : 0;
        __syncthreads();
        s[t] += tv;
        __syncthreads();
    }
    if (t < nb) g_bsum[t] = s[t] - v;
}

__global__ void k_scan_add(int n, int total) {
    int i = blockIdx.x * blockDim.x + threadIdx.x;
    if (i < n) {
        int v = g_rp[i] + g_bsum[i >> 10];
        g_rp[i] = v;
        g_cur[i] = v;
    }
    if (i == 0) g_rp[n] = total;
}

// ---------------- scatter edges into src-CSR order (store dst) --------------
__global__ void k_scatter(const void* __restrict__ ei, int E, int EN, int n) {
    int i = blockIdx.x * blockDim.x + threadIdx.x;
    if (i >= EN) return;
    int s, d;
    if (i < E) {
        s = clampi(load_idx(ei, i), n);
        d = clampi(load_idx(ei, (long long)E + i), n);
    } else { s = i - E; d = s; }
    int pos = atomicAdd(&g_cur[s], 1);
    if (pos >= 0 && pos < ENMAX) g_sd[pos] = d;
}

// ---------------- zero accumulators ------------------------------------------
__global__ void k_zeroacc(int n) {
    int total = n * 16;   // float4 count
    float4 z = make_float4(0.f, 0.f, 0.f, 0.f);
    for (int i = blockIdx.x * blockDim.x + threadIdx.x; i < total;
         i += gridDim.x * blockDim.x) {
        ((float4*)g_acc)[i] = z;
        if (i < n) { g_den[i] = 0.f; g_den2[i] = 0.f; }
    }
}

// ---------------- red helper --------------------------------------------------
__device__ __forceinline__ void red_v4(float* p, float a, float b, float c, float d) {
    asm volatile("red.global.add.v4.f32 [%0], {%1, %2, %3, %4};"
                 :: "l"(p), "f"(a), "f"(b), "f"(c), "f"(d) : "memory");
}

// ---------------- SGEMM1 (128->64) with FUSED softmax scatter (R13 form) -----
__global__ void __launch_bounds__(256)
k_sgemm128s(const float* __restrict__ X, const float* __restrict__ Wg, int n) {
    __shared__ float xs[64 * 68];   // staging (stride 64 + XOR) then out tile (stride 68)
    __shared__ float ws[64 * 64];
    __shared__ float sAS[64];
    __shared__ int   srp[65];

    int tid = threadIdx.x;
    int i = tid >> 4, j = tid & 15;
    int base = blockIdx.x * 64;

    if (tid < 64) sAS[tid] = g_as1[base + tid < n ? base + tid : n - 1];
    if (tid < 65) srp[tid] = g_rp[base + tid < n ? base + tid : n];

    float acc[4][4];
#pragma unroll
    for (int r = 0; r < 4; r++)
#pragma unroll
        for (int c = 0; c < 4; c++) acc[r][c] = 0.f;

#pragma unroll
    for (int ph = 0; ph < 2; ph++) {
        __syncthreads();
#pragma unroll
        for (int t = tid; t < 1024; t += 256) {
            int row = t >> 4, c4 = t & 15;
            int rc = base + row < n ? base + row : n - 1;
            float4 v = *(const float4*)(X + (size_t)rc * 128 + ph * 64 + c4 * 4);
            int g0 = row >> 2, r3 = row & 3;
#pragma unroll
            for (int s = 0; s < 4; s++) {
                int k = c4 * 4 + s;
                float val = (s == 0) ? v.x : (s == 1) ? v.y : (s == 2) ? v.z : v.w;
                xs[k * 64 + ((g0 ^ (k & 15)) << 2) + r3] = val;
            }
        }
#pragma unroll
        for (int t = tid; t < 1024; t += 256) {
            int k = t >> 4, c4 = t & 15;
            *(float4*)(ws + k * 64 + c4 * 4) =
                *(const float4*)(Wg + (size_t)(ph * 64 + k) * 64 + c4 * 4);
        }
        __syncthreads();

#pragma unroll 4
        for (int k = 0; k < 64; k++) {
            float4 a = *(const float4*)(xs + k * 64 + ((i ^ (k & 15)) << 2));
            float4 b = *(const float4*)(ws + k * 64 + j * 4);
            acc[0][0] += a.x * b.x; acc[0][1] += a.x * b.y;
            acc[0][2] += a.x * b.z; acc[0][3] += a.x * b.w;
            acc[1][0] += a.y * b.x; acc[1][1] += a.y * b.y;
            acc[1][2] += a.y * b.z; acc[1][3] += a.y * b.w;
            acc[2][0] += a.z * b.x; acc[2][1] += a.z * b.y;
            acc[2][2] += a.z * b.z; acc[2][3] += a.z * b.w;
            acc[3][0] += a.w * b.x; acc[3][1] += a.w * b.y;
            acc[3][2] += a.w * b.z; acc[3][3] += a.w * b.w;
        }
    }

    // ---- epilogue: stage out tile row-major (stride 68), then scatter ----
    __syncthreads();
#pragma unroll
    for (int rr = 0; rr < 4; rr++)
        *(float4*)(xs + (i * 4 + rr) * 68 + j * 4) =
            make_float4(acc[rr][0], acc[rr][1], acc[rr][2], acc[rr][3]);
    __syncthreads();

    int warp = tid >> 5, lane = tid & 31;
    int q = lane & 15, half = lane >> 4;
    for (int lr = warp * 8; lr < warp * 8 + 8; lr++) {
        int beg = srp[lr], end = srp[lr + 1];
        if (beg >= end) continue;
        float4 hv = *(const float4*)(xs + lr * 68 + q * 4);
        float as_v = sAS[lr];
        int jj = beg;
        for (; jj + 1 < end; jj += 2) {
            int d = g_sd[jj + half];
            float e = as_v + g_ad1[d];
            e = (e > 0.f) ? e : 0.2f * e;
            float w = __expf(e);
            float* ap = g_acc + (size_t)d * 64 + q * 4;
            red_v4(ap, w * hv.x, w * hv.y, w * hv.z, w * hv.w);
            if (q == 0) atomicAdd(&g_den[d], w);
        }
        if (jj < end && half == 0) {
            int d = g_sd[jj];
            float e = as_v + g_ad1[d];
            e = (e > 0.f) ? e : 0.2f * e;
            float w = __expf(e);
            float* ap = g_acc + (size_t)d * 64 + q * 4;
            red_v4(ap, w * hv.x, w * hv.y, w * hv.z, w * hv.w);
            if (q == 0) atomicAdd(&g_den[d], w);
        }
    }
}

// ---------------- layer-2 denominators + edge weights (warp per SRC) ---------
__global__ void __launch_bounds__(256)
k_den2(int n) {
    int src = (blockIdx.x * blockDim.x + threadIdx.x) >> 5;
    int lane = threadIdx.x & 31;
    if (src >= n) return;
    float as_v = g_as2[src];
    int beg = g_rp[src], end = g_rp[src + 1];
    for (int j = beg + lane; j < end; j += 32) {
        int d = g_sd[j];
        float e = as_v + g_ad2[d];
        e = (e > 0.f) ? e : 0.2f * e;
        float w = __expf(e);
        g_w[j] = w;
        atomicAdd(&g_den2[d], w);
    }
}

// ---------------- SGEMM2 (64->64) + fused norm input + FUSED coef-pool -------
// No H2 array: tile h2 stays in smem; epilogue computes a_src per row and
// accumulates a*h2_row into this block's pool partial.
__global__ void __launch_bounds__(256)
k_sgemm64fp(const float* __restrict__ Wg, const float* __restrict__ b1, int n) {
    __shared__ float xs[64 * 68];   // compute staging then h2 out-tile (stride 68)
    __shared__ float ws[64 * 64];
    __shared__ float bs[64];
    __shared__ float psum[8][64];
    __shared__ int   srp[65];

    int tid = threadIdx.x;
    int i = tid >> 4, j = tid & 15;
    int base = blockIdx.x * 64;

    if (tid < 64) bs[tid] = b1[tid];
    if (tid < 65) srp[tid] = g_rp[base + tid < n ? base + tid : n];
    __syncthreads();

    // X tile from g_acc with fused normalize+bias+relu; transposed+swizzled
#pragma unroll
    for (int t = tid; t < 1024; t += 256) {
        int row = t >> 4, c4 = t & 15;
        int rc = base + row < n ? base + row : n - 1;
        float inv = 1.f / (g_den[rc] + 1e-16f);
        float4 v = *(const float4*)(g_acc + (size_t)rc * 64 + c4 * 4);
        int g0 = row >> 2, r3 = row & 3;
#pragma unroll
        for (int s = 0; s < 4; s++) {
            int k = c4 * 4 + s;
            float val = (s == 0) ? v.x : (s == 1) ? v.y : (s == 2) ? v.z : v.w;
            val = fmaxf(val * inv + bs[k], 0.f);
            xs[k * 64 + ((g0 ^ (k & 15)) << 2) + r3] = val;
        }
    }
#pragma unroll
    for (int t = tid; t < 1024; t += 256) {
        int k = t >> 4, c4 = t & 15;
        *(float4*)(ws + k * 64 + c4 * 4) =
            *(const float4*)(Wg + (size_t)k * 64 + c4 * 4);
    }
    __syncthreads();

    float acc[4][4];
#pragma unroll
    for (int r = 0; r < 4; r++)
#pragma unroll
        for (int c = 0; c < 4; c++) acc[r][c] = 0.f;

#pragma unroll 4
    for (int k = 0; k < 64; k++) {
        float4 a = *(const float4*)(xs + k * 64 + ((i ^ (k & 15)) << 2));
        float4 b = *(const float4*)(ws + k * 64 + j * 4);
        acc[0][0] += a.x * b.x; acc[0][1] += a.x * b.y;
        acc[0][2] += a.x * b.z; acc[0][3] += a.x * b.w;
        acc[1][0] += a.y * b.x; acc[1][1] += a.y * b.y;
        acc[1][2] += a.y * b.z; acc[1][3] += a.y * b.w;
        acc[2][0] += a.z * b.x; acc[2][1] += a.z * b.y;
        acc[2][2] += a.z * b.z; acc[2][3] += a.z * b.w;
        acc[3][0] += a.w * b.x; acc[3][1] += a.w * b.y;
        acc[3][2] += a.w * b.z; acc[3][3] += a.w * b.w;
    }

    // ---- stage h2 tile row-major (stride 68) ----
    __syncthreads();
#pragma unroll
    for (int rr = 0; rr < 4; rr++)
        *(float4*)(xs + (i * 4 + rr) * 68 + j * 4) =
            make_float4(acc[rr][0], acc[rr][1], acc[rr][2], acc[rr][3]);
    __syncthreads();

    // ---- epilogue: per-row coefficient a_src, pool-accumulate a*h2_row ----
    int warp = tid >> 5, lane = tid & 31;
    float p0 = 0.f, p1 = 0.f;
    for (int lr = warp * 8; lr < warp * 8 + 8; lr++) {
        int row = base + lr;
        if (row >= n) break;
        int beg = srp[lr], end = srp[lr + 1];
        float a = 0.f;
        for (int jj = beg + lane; jj < end; jj += 32)
            a += g_w[jj] / (g_den2[g_sd[jj]] + 1e-16f);
#pragma unroll
        for (int o = 16; o; o >>= 1) a += __shfl_xor_sync(0xffffffffu, a, o);
        p0 += a * xs[lr * 68 + lane];
        p1 += a * xs[lr * 68 + lane + 32];
    }
    psum[warp][lane] = p0;
    psum[warp][lane + 32] = p1;
    __syncthreads();
    if (tid < 64) {
        float v = 0.f;
#pragma unroll
        for (int w = 0; w < 8; w++) v += psum[w][tid];
        g_pool[blockIdx.x * 64 + tid] = v;
    }
}

// ---------------- final reduce + bias ----------------------------------------
__global__ void k_pool_b(const float* __restrict__ b2, float* __restrict__ out,
                         int n, int nblocks) {
    int col = threadIdx.x;   // 64 threads
    float acc = 0.f;
    for (int b = 0; b < nblocks; b++) acc += g_pool[b * 64 + col];
    out[col] = acc * (1.0f / (float)n) + b2[col];
}

// ---------------- launch ----------------------------------------------------
extern "C" void kernel_launch(void* const* d_in, const int* in_sizes, int n_in,
                              void* d_out, int out_size) {
    const float* x   = (const float*)d_in[0];
    const void*  ei  = d_in[1];
    const float* W1  = (const float*)d_in[3];
    const float* as1 = (const float*)d_in[4];
    const float* ad1 = (const float*)d_in[5];
    const float* b1  = (const float*)d_in[6];
    const float* W2  = (const float*)d_in[7];
    const float* as2 = (const float*)d_in[8];
    const float* ad2 = (const float*)d_in[9];
    const float* b2  = (const float*)d_in[10];
    float* out = (float*)d_out;

    int n  = in_sizes[0] / 128;   // N nodes
    int E  = in_sizes[1] / 2;     // edges
    int EN = E + n;               // edges + self loops

    int sgemmBlocks = (n + 63) / 64;
    int aggBlocks   = (n + 7) / 8;
    int nb          = (n + 1023) / 1024;

    k_zero<<<(n + 255) / 256, 256>>>(n);
    int nq = E < 2048 ? E : 2048;
    k_detect<<<(nq + 255) / 256, 256>>>((const long long*)ei, nq);
    k_wv1<<<1, 128>>>(W1, as1, ad1);
    k_mv1<<<(n + 31) / 32, 256>>>(x, n);
    k_hist<<<(EN + 255) / 256, 256>>>(ei, E, EN, n);
    k_scan_block<<<nb, 1024>>>(n);
    k_scan_top<<<1, 128>>>(nb);
    k_scan_add<<<(n + 255) / 256, 256>>>(n, EN);
    k_scatter<<<(EN + 255) / 256, 256>>>(ei, E, EN, n);
    k_zeroacc<<<480, 256>>>(n);

    // --- layer 1: GEMM with fused softmax scatter (R13 half-warp epilogue) ---
    k_sgemm128s<<<sgemmBlocks, 256>>>(x, W1, n);

    // --- layer 2: AS2/AD2 via mv-trick, den2, GEMM with fused coef-pool ---
    k_wv2<<<1, 64>>>(W2, as2, ad2);
    k_mv2<<<(n + 63) / 64, 256>>>(b1, n);
    k_den2<<<aggBlocks, 256>>>(n);
    k_sgemm64fp<<<sgemmBlocks, 256>>>(W2, b1, n);
    k_pool_b<<<1, 64>>>(b2, out, n, sgemmBlocks);
}